// round 4
// baseline (speedup 1.0000x reference)
#include <cuda_runtime.h>
#include <cstdint>

// p-bit Glauber sequential update, N=4096 spins, 16384 steps.
// K0: thr[t]=atanh(2u-1) zipped with idx  (tanh(F)>=r  <=>  F>=atanh(r))
// K1: F = J@m0 + h (parallel; warms L2 with the 64MB J matrix)
// K2: single-CTA anchored-window speculation:
//     - authoritative F lives in REGISTERS (8 elems/thread); smem holds a
//       write-only-published mirror for scattered reads -> per-flip smem cost
//       is 16KB STS only (no read-modify-write).
//     - window of 512 steps in registers (thr, idx, spin copy);
//     - per round: scan ballots -> first flip f1 + candidate f2; apply f1's
//       rank-1 row update from prefetch registers (row prefetched last round),
//       prefetch f2's row; re-evaluate only threads > f1.

#define NN      4096
#define NSTEPS  16384
#define TPB     512
#define NWARPS  (TPB / 32)

__device__ float  g_F[NN];
__device__ float2 g_TI[NSTEPS];   // {thr, idx-as-float-bits}

// ---------------------------------------------------------------------------
__global__ void prep_thresholds(const int* __restrict__ idx,
                                const float* __restrict__ u) {
    const int t = blockIdx.x * blockDim.x + threadIdx.x;
    if (t < NSTEPS) {
        const float r = 2.0f * u[t] - 1.0f;
        g_TI[t] = make_float2(atanhf(r), __int_as_float(idx[t]));
    }
}

// ---------------------------------------------------------------------------
__global__ void init_field(const float* __restrict__ J,
                           const float* __restrict__ h,
                           const float* __restrict__ m0) {
    const int row = blockIdx.x;
    const float4* __restrict__ Jr = reinterpret_cast<const float4*>(J) + (size_t)row * (NN / 4);
    const float4* __restrict__ M4 = reinterpret_cast<const float4*>(m0);

    float sum = 0.0f;
    for (int k = threadIdx.x; k < NN / 4; k += blockDim.x) {
        float4 a = Jr[k];
        float4 b = M4[k];
        sum += a.x * b.x + a.y * b.y + a.z * b.z + a.w * b.w;
    }
    #pragma unroll
    for (int off = 16; off; off >>= 1)
        sum += __shfl_xor_sync(0xffffffffu, sum, off);

    __shared__ float ws[8];
    const int lane = threadIdx.x & 31;
    const int wid  = threadIdx.x >> 5;
    if (lane == 0) ws[wid] = sum;
    __syncthreads();
    if (threadIdx.x == 0) {
        float tot = 0.0f;
        #pragma unroll
        for (int w = 0; w < 8; w++) tot += ws[w];
        g_F[row] = tot + h[row];
    }
}

// ---------------------------------------------------------------------------
__global__ __launch_bounds__(TPB, 1)
void pbit_dynamics(const float* __restrict__ J,
                   const float* __restrict__ m0,
                   float*       __restrict__ out) {
    __shared__ float F_sh[NN];     // mirror (write-publish only after init)
    __shared__ float m_sh[NN];
    __shared__ int   win_idx[TPB];
    __shared__ __align__(16) unsigned fbal[NWARPS];
    __shared__ __align__(16) unsigned sbal[NWARPS];

    const int tid  = threadIdx.x;
    const int lane = tid & 31;
    const int wid  = tid >> 5;

    // authoritative F: 8 contiguous elements per thread
    const float4* gF4 = reinterpret_cast<const float4*>(g_F);
    float4* F4 = reinterpret_cast<float4*>(F_sh);
    float4 Fa = gF4[2 * tid];
    float4 Fb = gF4[2 * tid + 1];
    F4[2 * tid]     = Fa;
    F4[2 * tid + 1] = Fb;
    for (int k = tid; k < NN; k += TPB)
        m_sh[k] = m0[k];
    __syncthreads();

    for (int t = 0; t < NSTEPS; t += TPB) {
        // ---- window load: registers, once ----
        const float2 ti   = g_TI[t + tid];
        const float my_thr = ti.x;
        const int   my_i   = __float_as_int(ti.y);
        win_idx[tid] = my_i;
        float my_m = m_sh[my_i];

        bool spos = (F_sh[my_i] >= my_thr);
        bool flip = spos != (my_m > 0.0f);
        unsigned fb = __ballot_sync(0xffffffffu, flip);
        unsigned sb = __ballot_sync(0xffffffffu, spos);
        if (lane == 0) { fbal[wid] = fb; sbal[wid] = sb; }
        __syncthreads();

        int    pf_f = -1;
        float4 p0, p1;

        for (;;) {
            // ---- scan ballots: first two flip positions ----
            unsigned w16[NWARPS];
            {
                const uint4* v = reinterpret_cast<const uint4*>(fbal);
                #pragma unroll
                for (int q = 0; q < NWARPS / 4; q++) {
                    uint4 x = v[q];
                    w16[4 * q]     = x.x;
                    w16[4 * q + 1] = x.y;
                    w16[4 * q + 2] = x.z;
                    w16[4 * q + 3] = x.w;
                }
            }
            int f1 = -1, f2 = -1;
            #pragma unroll
            for (int w = 0; w < NWARPS; w++) {
                unsigned b = w16[w];
                if (b) {
                    if (f1 < 0) {
                        f1 = (w << 5) + __ffs(b) - 1;
                        b &= b - 1;
                        if (b) f2 = (w << 5) + __ffs(b) - 1;
                    } else if (f2 < 0) {
                        f2 = (w << 5) + __ffs(b) - 1;
                    }
                }
            }
            if (f1 < 0) break;

            const int   i1 = win_idx[f1];
            const float s1 = ((sbal[f1 >> 5] >> (f1 & 31)) & 1u) ? 1.0f : -1.0f;
            const float d  = 2.0f * s1;

            float4 r0, r1;
            if (pf_f == f1) {                       // speculation hit
                r0 = p0; r1 = p1;
            } else {                                // miss: blocking fetch
                const float4* __restrict__ Jr =
                    reinterpret_cast<const float4*>(J) + (size_t)i1 * (NN / 4);
                r0 = Jr[2 * tid];
                r1 = Jr[2 * tid + 1];
            }
            if (f2 >= 0) {                          // prefetch next candidate
                const int i2 = win_idx[f2];
                const float4* __restrict__ Jp =
                    reinterpret_cast<const float4*>(J) + (size_t)i2 * (NN / 4);
                p0 = Jp[2 * tid];
                p1 = Jp[2 * tid + 1];
                pf_f = f2;
            } else {
                pf_f = -1;
            }

            // ---- rank-1 update in registers; write-only publish to smem ----
            Fa.x += r0.x * d; Fa.y += r0.y * d; Fa.z += r0.z * d; Fa.w += r0.w * d;
            Fb.x += r1.x * d; Fb.y += r1.y * d; Fb.z += r1.z * d; Fb.w += r1.w * d;
            F4[2 * tid]     = Fa;
            F4[2 * tid + 1] = Fb;

            if (my_i == i1) my_m = s1;
            if (tid == f1)  m_sh[i1] = s1;
            __syncthreads();

            // ---- re-evaluate only unresolved steps ----
            bool spos2 = false, flip2 = false;
            if (tid > f1) {
                spos2 = (F_sh[my_i] >= my_thr);
                flip2 = spos2 != (my_m > 0.0f);
            }
            fb = __ballot_sync(0xffffffffu, flip2);
            sb = __ballot_sync(0xffffffffu, spos2);
            if (lane == 0) { fbal[wid] = fb; sbal[wid] = sb; }
            __syncthreads();
        }
    }

    for (int k = tid; k < NN; k += TPB)
        out[k] = m_sh[k];
}

// ---------------------------------------------------------------------------
extern "C" void kernel_launch(void* const* d_in, const int* in_sizes, int n_in,
                              void* d_out, int out_size) {
    const float* J  = (const float*)d_in[0];
    const float* h  = (const float*)d_in[1];
    const float* m0 = (const float*)d_in[2];
    const int*   idx= (const int*)  d_in[3];
    const float* u  = (const float*)d_in[4];
    float* out = (float*)d_out;

    prep_thresholds<<<NSTEPS / 256, 256>>>(idx, u);
    init_field<<<NN, 256>>>(J, h, m0);
    pbit_dynamics<<<1, TPB>>>(J, m0, out);
}

// round 5
// speedup vs baseline: 1.1446x; 1.1446x over previous
#include <cuda_runtime.h>
#include <cstdint>

// p-bit Glauber sequential update, N=4096 spins, 16384 steps.
// K0: thr[t]=atanh(2u-1) zipped with idx  (tanh(F)>=r  <=>  F>=atanh(r))
// K1: F = J@m0 + h (parallel; warms L2 with the 64MB J matrix)
// K2: single-CTA anchored-window speculation:
//     - authoritative F in REGISTERS, conflict-free layout: thread owns
//       F4[tid] and F4[tid+TPB] (contiguous per warp). smem mirror is
//       write-only published (no read-modify-write on the flip path).
//     - window of 512 steps in registers (thr, idx, spin copy);
//     - per round: scan ballots -> first flip f1 + candidate f2; apply f1's
//       row from prefetch registers (prefetched last round), prefetch f2's
//       row; re-evaluate only threads > f1.

#define NN      4096
#define NSTEPS  16384
#define TPB     512
#define NWARPS  (TPB / 32)

__device__ float  g_F[NN];
__device__ float2 g_TI[NSTEPS];   // {thr, idx-as-float-bits}

// ---------------------------------------------------------------------------
__global__ void prep_thresholds(const int* __restrict__ idx,
                                const float* __restrict__ u) {
    const int t = blockIdx.x * blockDim.x + threadIdx.x;
    if (t < NSTEPS) {
        const float r = 2.0f * u[t] - 1.0f;
        g_TI[t] = make_float2(atanhf(r), __int_as_float(idx[t]));
    }
}

// ---------------------------------------------------------------------------
__global__ void init_field(const float* __restrict__ J,
                           const float* __restrict__ h,
                           const float* __restrict__ m0) {
    const int row = blockIdx.x;
    const float4* __restrict__ Jr = reinterpret_cast<const float4*>(J) + (size_t)row * (NN / 4);
    const float4* __restrict__ M4 = reinterpret_cast<const float4*>(m0);

    float sum = 0.0f;
    for (int k = threadIdx.x; k < NN / 4; k += blockDim.x) {
        float4 a = Jr[k];
        float4 b = M4[k];
        sum += a.x * b.x + a.y * b.y + a.z * b.z + a.w * b.w;
    }
    #pragma unroll
    for (int off = 16; off; off >>= 1)
        sum += __shfl_xor_sync(0xffffffffu, sum, off);

    __shared__ float ws[8];
    const int lane = threadIdx.x & 31;
    const int wid  = threadIdx.x >> 5;
    if (lane == 0) ws[wid] = sum;
    __syncthreads();
    if (threadIdx.x == 0) {
        float tot = 0.0f;
        #pragma unroll
        for (int w = 0; w < 8; w++) tot += ws[w];
        g_F[row] = tot + h[row];
    }
}

// ---------------------------------------------------------------------------
__global__ __launch_bounds__(TPB, 1)
void pbit_dynamics(const float* __restrict__ J,
                   const float* __restrict__ m0,
                   float*       __restrict__ out) {
    __shared__ float F_sh[NN];     // mirror: write-published, scatter-read
    __shared__ float m_sh[NN];
    __shared__ int   win_idx[TPB];
    __shared__ __align__(16) unsigned fbal[NWARPS];
    __shared__ __align__(16) unsigned sbal[NWARPS];

    const int tid  = threadIdx.x;
    const int lane = tid & 31;
    const int wid  = tid >> 5;

    // authoritative F in registers; ownership [tid], [tid+TPB] (conflict-free)
    const float4* gF4 = reinterpret_cast<const float4*>(g_F);
    float4* F4 = reinterpret_cast<float4*>(F_sh);
    float4 Fa = gF4[tid];
    float4 Fb = gF4[tid + TPB];
    F4[tid]       = Fa;
    F4[tid + TPB] = Fb;
    for (int k = tid; k < NN; k += TPB)
        m_sh[k] = m0[k];
    __syncthreads();

    for (int t = 0; t < NSTEPS; t += TPB) {
        // ---- window load: registers, once ----
        const float2 ti    = g_TI[t + tid];
        const float my_thr = ti.x;
        const int   my_i   = __float_as_int(ti.y);
        win_idx[tid] = my_i;
        float my_m = m_sh[my_i];

        bool spos = (F_sh[my_i] >= my_thr);
        bool flip = spos != (my_m > 0.0f);
        unsigned fb = __ballot_sync(0xffffffffu, flip);
        unsigned sb = __ballot_sync(0xffffffffu, spos);
        if (lane == 0) { fbal[wid] = fb; sbal[wid] = sb; }
        __syncthreads();

        int    pf_f = -1;
        float4 p0, p1;

        for (;;) {
            // ---- scan ballots: first two flip positions ----
            unsigned w16[NWARPS];
            {
                const uint4* v = reinterpret_cast<const uint4*>(fbal);
                #pragma unroll
                for (int q = 0; q < NWARPS / 4; q++) {
                    uint4 x = v[q];
                    w16[4 * q]     = x.x;
                    w16[4 * q + 1] = x.y;
                    w16[4 * q + 2] = x.z;
                    w16[4 * q + 3] = x.w;
                }
            }
            int f1 = -1, f2 = -1;
            #pragma unroll
            for (int w = 0; w < NWARPS; w++) {
                unsigned b = w16[w];
                if (b) {
                    if (f1 < 0) {
                        f1 = (w << 5) + __ffs(b) - 1;
                        b &= b - 1;
                        if (b) f2 = (w << 5) + __ffs(b) - 1;
                    } else if (f2 < 0) {
                        f2 = (w << 5) + __ffs(b) - 1;
                    }
                }
            }
            if (f1 < 0) break;

            const int   i1 = win_idx[f1];
            const float s1 = ((sbal[f1 >> 5] >> (f1 & 31)) & 1u) ? 1.0f : -1.0f;
            const float d  = 2.0f * s1;

            float4 r0, r1;
            if (pf_f == f1) {                       // speculation hit
                r0 = p0; r1 = p1;
            } else {                                // miss: blocking fetch
                const float4* __restrict__ Jr =
                    reinterpret_cast<const float4*>(J) + (size_t)i1 * (NN / 4);
                r0 = Jr[tid];
                r1 = Jr[tid + TPB];
            }
            if (f2 >= 0) {                          // prefetch next candidate
                const int i2 = win_idx[f2];
                const float4* __restrict__ Jp =
                    reinterpret_cast<const float4*>(J) + (size_t)i2 * (NN / 4);
                p0 = Jp[tid];
                p1 = Jp[tid + TPB];
                pf_f = f2;
            } else {
                pf_f = -1;
            }

            // ---- rank-1 update in registers; write-only publish ----
            Fa.x += r0.x * d; Fa.y += r0.y * d; Fa.z += r0.z * d; Fa.w += r0.w * d;
            Fb.x += r1.x * d; Fb.y += r1.y * d; Fb.z += r1.z * d; Fb.w += r1.w * d;
            F4[tid]       = Fa;
            F4[tid + TPB] = Fb;

            if (my_i == i1) my_m = s1;
            if (tid == f1)  m_sh[i1] = s1;
            __syncthreads();

            // ---- re-evaluate only unresolved steps ----
            bool spos2 = false, flip2 = false;
            if (tid > f1) {
                spos2 = (F_sh[my_i] >= my_thr);
                flip2 = spos2 != (my_m > 0.0f);
            }
            fb = __ballot_sync(0xffffffffu, flip2);
            sb = __ballot_sync(0xffffffffu, spos2);
            if (lane == 0) { fbal[wid] = fb; sbal[wid] = sb; }
            __syncthreads();
        }
    }

    for (int k = tid; k < NN; k += TPB)
        out[k] = m_sh[k];
}

// ---------------------------------------------------------------------------
extern "C" void kernel_launch(void* const* d_in, const int* in_sizes, int n_in,
                              void* d_out, int out_size) {
    const float* J  = (const float*)d_in[0];
    const float* h  = (const float*)d_in[1];
    const float* m0 = (const float*)d_in[2];
    const int*   idx= (const int*)  d_in[3];
    const float* u  = (const float*)d_in[4];
    float* out = (float*)d_out;

    prep_thresholds<<<NSTEPS / 256, 256>>>(idx, u);
    init_field<<<NN, 256>>>(J, h, m0);
    pbit_dynamics<<<1, TPB>>>(J, m0, out);
}

// round 6
// speedup vs baseline: 1.6956x; 1.4813x over previous
#include <cuda_runtime.h>
#include <cstdint>

// p-bit Glauber sequential update, N=4096 spins, 16384 steps.
// K0: thr[t]=atanh(2u-1) zipped with idx  (tanh(F)>=r  <=>  F>=atanh(r))
// K1: F = J@m0 + h (parallel; warms L2 with the 64MB J matrix)
// K2: single-CTA, register-field speculation:
//   - F lives in registers (8/thread). Published to smem ONLY at window
//     anchors (every 64 steps), not per flip.
//   - 64 evaluator threads keep fF = F[my_i] in a register; per flip it is
//     updated by ONE scalar fmaf with J[i1][my_i] (prefetched for the
//     predicted next flip). No smem F traffic, ONE barrier per flip
//     (ping-pong ballot buffers).
//   - owners apply the rank-1 row to their register F with prefetched rows.

#define NN      4096
#define NSTEPS  16384
#define TPB     512
#define W       64            // evaluator window width
#define FULLM   0xffffffffu

__device__ float  g_F[NN];
__device__ float2 g_TI[NSTEPS];   // {thr, idx-as-float-bits}

// ---------------------------------------------------------------------------
__global__ void prep_thresholds(const int* __restrict__ idx,
                                const float* __restrict__ u) {
    const int t = blockIdx.x * blockDim.x + threadIdx.x;
    if (t < NSTEPS) {
        const float r = 2.0f * u[t] - 1.0f;
        g_TI[t] = make_float2(atanhf(r), __int_as_float(idx[t]));
    }
}

// ---------------------------------------------------------------------------
__global__ void init_field(const float* __restrict__ J,
                           const float* __restrict__ h,
                           const float* __restrict__ m0) {
    const int row = blockIdx.x;
    const float4* __restrict__ Jr = reinterpret_cast<const float4*>(J) + (size_t)row * (NN / 4);
    const float4* __restrict__ M4 = reinterpret_cast<const float4*>(m0);

    float sum = 0.0f;
    for (int k = threadIdx.x; k < NN / 4; k += blockDim.x) {
        float4 a = Jr[k];
        float4 b = M4[k];
        sum += a.x * b.x + a.y * b.y + a.z * b.z + a.w * b.w;
    }
    #pragma unroll
    for (int off = 16; off; off >>= 1)
        sum += __shfl_xor_sync(FULLM, sum, off);

    __shared__ float ws[8];
    const int lane = threadIdx.x & 31;
    const int wid  = threadIdx.x >> 5;
    if (lane == 0) ws[wid] = sum;
    __syncthreads();
    if (threadIdx.x == 0) {
        float tot = 0.0f;
        #pragma unroll
        for (int w = 0; w < 8; w++) tot += ws[w];
        g_F[row] = tot + h[row];
    }
}

// ---------------------------------------------------------------------------
__global__ __launch_bounds__(TPB, 1)
void pbit_dynamics(const float* __restrict__ J,
                   const float* __restrict__ m0,
                   float*       __restrict__ out) {
    __shared__ float F_sh[NN];            // refreshed only at anchors
    __shared__ float m_sh[NN];
    __shared__ int   win_idx[W];
    __shared__ unsigned fbal[2][2];       // ping-pong ballots (W=64 -> 2 words)
    __shared__ unsigned sbal[2][2];

    const int tid  = threadIdx.x;
    const int lane = tid & 31;
    const int wid  = tid >> 5;

    // register-resident F: thread owns F4[tid] and F4[tid+TPB]
    const float4* gF4 = reinterpret_cast<const float4*>(g_F);
    float4* F4 = reinterpret_cast<float4*>(F_sh);
    float4 Fa = gF4[tid];
    float4 Fb = gF4[tid + TPB];
    for (int k = tid; k < NN; k += TPB)
        m_sh[k] = m0[k];

    float2 tiPF = make_float2(0.0f, 0.0f);
    if (tid < W) tiPF = g_TI[tid];        // first window prefetch

    for (int t = 0; t < NSTEPS; t += W) {
        // ---- anchor: publish F, load window into registers ----
        F4[tid]       = Fa;
        F4[tid + TPB] = Fb;
        __syncthreads();

        float my_thr = 0.0f, my_m = 0.0f, fF = 0.0f;
        int   my_i = 0;
        bool  flip = false, spos = false;
        if (tid < W) {
            my_thr = tiPF.x;
            my_i   = __float_as_int(tiPF.y);
            win_idx[tid] = my_i;
            my_m = m_sh[my_i];
            fF   = F_sh[my_i];
            spos = (fF >= my_thr);
            flip = spos != (my_m > 0.0f);
        }
        unsigned fb = __ballot_sync(FULLM, flip);
        unsigned sb = __ballot_sync(FULLM, spos);
        if (lane == 0 && wid < 2) { fbal[0][wid] = fb; sbal[0][wid] = sb; }
        if (tid < W && t + W < NSTEPS) tiPF = g_TI[t + W + tid];  // next-window prefetch
        __syncthreads();

        int    par = 0;
        int    pf  = -1;       // predicted next flip position
        float  pJ  = 0.0f;     // prefetched scalar J[i2][my_i]
        float4 pr0, pr1;       // prefetched row chunks

        for (;;) {
            const unsigned b0 = fbal[par][0];
            const unsigned b1 = fbal[par][1];
            const int f1 = b0 ? (__ffs(b0) - 1) : (b1 ? 32 + __ffs(b1) - 1 : -1);
            if (f1 < 0) break;

            unsigned c0 = b0, c1 = b1;
            if (f1 < 32) c0 &= c0 - 1; else c1 &= c1 - 1;
            const int f2 = c0 ? (__ffs(c0) - 1) : (c1 ? 32 + __ffs(c1) - 1 : -1);

            const int   i1 = win_idx[f1];
            const float s1 = ((sbal[par][f1 >> 5] >> (f1 & 31)) & 1u) ? 1.0f : -1.0f;
            const float d  = 2.0f * s1;

            // owner row (prefetched on hit)
            float4 r0, r1;
            if (pf == f1) { r0 = pr0; r1 = pr1; }
            else {
                const float4* __restrict__ Jr =
                    reinterpret_cast<const float4*>(J) + (size_t)i1 * (NN / 4);
                r0 = Jr[tid];
                r1 = Jr[tid + TPB];
            }
            // evaluator scalar (prefetched on hit)
            float jv = 0.0f;
            if (tid < W)
                jv = (pf == f1) ? pJ : __ldg(J + (size_t)i1 * NN + my_i);

            // prefetch for predicted next flip f2
            if (f2 >= 0) {
                const int i2 = win_idx[f2];
                const float4* __restrict__ Jp =
                    reinterpret_cast<const float4*>(J) + (size_t)i2 * (NN / 4);
                pr0 = Jp[tid];
                pr1 = Jp[tid + TPB];
                if (tid < W) pJ = __ldg(J + (size_t)i2 * NN + my_i);
                pf = f2;
            } else {
                pf = -1;
            }

            // owners: rank-1 update in registers only
            Fa.x = fmaf(r0.x, d, Fa.x);
            Fa.y = fmaf(r0.y, d, Fa.y);
            Fa.z = fmaf(r0.z, d, Fa.z);
            Fa.w = fmaf(r0.w, d, Fa.w);
            Fb.x = fmaf(r1.x, d, Fb.x);
            Fb.y = fmaf(r1.y, d, Fb.y);
            Fb.z = fmaf(r1.z, d, Fb.z);
            Fb.w = fmaf(r1.w, d, Fb.w);

            // evaluators: scalar field update + re-decision
            bool nflip = false, nspos = false;
            if (tid < W) {
                fF = fmaf(jv, d, fF);
                if (my_i == i1) my_m = s1;
                if (tid > f1) {
                    nspos = (fF >= my_thr);
                    nflip = nspos != (my_m > 0.0f);
                }
            }
            const unsigned nfb = __ballot_sync(FULLM, nflip);
            const unsigned nsb = __ballot_sync(FULLM, nspos);
            if (lane == 0 && wid < 2) { fbal[par ^ 1][wid] = nfb; sbal[par ^ 1][wid] = nsb; }
            if (tid == f1) m_sh[i1] = s1;
            __syncthreads();
            par ^= 1;
        }
    }

    for (int k = tid; k < NN; k += TPB)
        out[k] = m_sh[k];
}

// ---------------------------------------------------------------------------
extern "C" void kernel_launch(void* const* d_in, const int* in_sizes, int n_in,
                              void* d_out, int out_size) {
    const float* J  = (const float*)d_in[0];
    const float* h  = (const float*)d_in[1];
    const float* m0 = (const float*)d_in[2];
    const int*   idx= (const int*)  d_in[3];
    const float* u  = (const float*)d_in[4];
    float* out = (float*)d_out;

    prep_thresholds<<<NSTEPS / 256, 256>>>(idx, u);
    init_field<<<NN, 256>>>(J, h, m0);
    pbit_dynamics<<<1, TPB>>>(J, m0, out);
}